// round 7
// baseline (speedup 1.0000x reference)
#include <cuda_runtime.h>
#include <math.h>
#include <stdint.h>

#define B_   64
#define Q_   512
#define KK_  512
#define C_   256
#define H_   8
#define HD_  32
#define OUT_ 256
#define SCALE_Q 0.17677669529663687f   // 1/sqrt(32)

// ---------------- scratch (static device globals; no allocation) -------------
__device__ __align__(16) float g_q[B_ * Q_ * C_];     // tf32-rounded scaled q
__device__ __align__(16) float g_gate[B_ * Q_ * C_];  // sigmoid gate (fp32)
__device__ __align__(16) float g_k[B_ * KK_ * C_];    // tf32-rounded k
__device__ __align__(16) float g_v[B_ * KK_ * C_];    // tf32-rounded v
__device__ __align__(16) float g_wa[B_ * Q_ * C_];    // gated weighted avg (fp32)

// ---------------- tf32 / mma / cp.async helpers -------------------------------
__device__ __forceinline__ uint32_t f2tf(float x) {
    uint32_t u;
    asm("cvt.rna.tf32.f32 %0, %1;" : "=r"(u) : "f"(x));
    return u;
}
__device__ __forceinline__ void cvt4(uint32_t* d, float4 v) {
    d[0] = f2tf(v.x); d[1] = f2tf(v.y); d[2] = f2tf(v.z); d[3] = f2tf(v.w);
}
__device__ __forceinline__ void mma8(float* d, const uint32_t* a, const uint32_t* b) {
    asm volatile(
        "mma.sync.aligned.m16n8k8.row.col.f32.tf32.tf32.f32 "
        "{%0,%1,%2,%3}, {%4,%5,%6,%7}, {%8,%9}, {%0,%1,%2,%3};"
        : "+f"(d[0]), "+f"(d[1]), "+f"(d[2]), "+f"(d[3])
        : "r"(a[0]), "r"(a[1]), "r"(a[2]), "r"(a[3]), "r"(b[0]), "r"(b[1]));
}
__device__ __forceinline__ void cp16(uint32_t dst, const float* src) {
    asm volatile("cp.async.ca.shared.global [%0], [%1], 16;" :: "r"(dst), "l"(src));
}
#define CP_COMMIT() asm volatile("cp.async.commit_group;")
#define CP_WAIT1()  asm volatile("cp.async.wait_group 1;")

// ---------------- tf32 projection GEMM, register-prefetch pipeline -----------
#define LDA 36
#define LDB 72
template <int MODE>
__global__ void __launch_bounds__(256) proj_tc(const float* __restrict__ A,
                                               const float* __restrict__ W0,
                                               const float* __restrict__ W1,
                                               const float* __restrict__ bvec,
                                               float* __restrict__ Dout) {
    __shared__ uint32_t As[128 * LDA];
    __shared__ uint32_t Bs[32 * LDB];

    const int tid  = threadIdx.x;
    const int m0   = blockIdx.x * 128;
    const int bn   = blockIdx.y;
    const int warp = tid >> 5, lane = tid & 31;
    const int g = lane >> 2, t = lane & 3;
    const int wm = warp >> 1, wn = warp & 1;

    const float* Ap = (MODE == 2) ? g_wa : A;
    const float* W  = (MODE == 2) ? W0 : (bn < 4 ? W0 : W1);
    const int ncol  = (MODE == 2) ? bn * 64 : (bn & 3) * 64;

    // per-thread load coords
    const int ar[4] = {tid >> 3, (256 + tid) >> 3, (512 + tid) >> 3, (768 + tid) >> 3};
    const int ac = (tid & 7) * 4;
    const int br_[2] = {tid >> 4, (256 + tid) >> 4};
    const int bc = (tid & 15) * 4;

    float acc[2][4][4];
#pragma unroll
    for (int i = 0; i < 2; i++)
#pragma unroll
        for (int j = 0; j < 4; j++)
#pragma unroll
            for (int c = 0; c < 4; c++) acc[i][j][c] = 0.0f;

    // prologue: load + store tile 0
    float4 ra[4], rb[2];
#pragma unroll
    for (int i = 0; i < 4; i++)
        ra[i] = *(const float4*)(Ap + (size_t)(m0 + ar[i]) * 256 + ac);
#pragma unroll
    for (int i = 0; i < 2; i++)
        rb[i] = *(const float4*)(W + (size_t)br_[i] * 256 + ncol + bc);
#pragma unroll
    for (int i = 0; i < 4; i++) {
        uint32_t u[4]; cvt4(u, ra[i]);
        *(uint4*)&As[ar[i] * LDA + ac] = *(uint4*)u;
    }
#pragma unroll
    for (int i = 0; i < 2; i++) {
        uint32_t u[4]; cvt4(u, rb[i]);
        *(uint4*)&Bs[br_[i] * LDB + bc] = *(uint4*)u;
    }

    for (int it = 0; it < 8; it++) {
        __syncthreads();
        // prefetch next tile into registers (overlaps mma below)
        if (it < 7) {
            const int k0 = (it + 1) * 32;
#pragma unroll
            for (int i = 0; i < 4; i++)
                ra[i] = *(const float4*)(Ap + (size_t)(m0 + ar[i]) * 256 + k0 + ac);
#pragma unroll
            for (int i = 0; i < 2; i++)
                rb[i] = *(const float4*)(W + (size_t)(k0 + br_[i]) * 256 + ncol + bc);
        }

#pragma unroll
        for (int kk = 0; kk < 4; kk++) {
            const int k8 = kk * 8;
            uint32_t af[2][4], bf[4][2];
#pragma unroll
            for (int i = 0; i < 2; i++) {
                const int rb2 = wm * 32 + i * 16;
                af[i][0] = As[(rb2 + g) * LDA + k8 + t];
                af[i][1] = As[(rb2 + g + 8) * LDA + k8 + t];
                af[i][2] = As[(rb2 + g) * LDA + k8 + t + 4];
                af[i][3] = As[(rb2 + g + 8) * LDA + k8 + t + 4];
            }
#pragma unroll
            for (int j = 0; j < 4; j++) {
                const int nb = wn * 32 + j * 8;
                bf[j][0] = Bs[(k8 + t) * LDB + nb + g];
                bf[j][1] = Bs[(k8 + t + 4) * LDB + nb + g];
            }
#pragma unroll
            for (int i = 0; i < 2; i++)
#pragma unroll
                for (int j = 0; j < 4; j++) mma8(acc[i][j], af[i], bf[j]);
        }
        __syncthreads();
        if (it < 7) {
#pragma unroll
            for (int i = 0; i < 4; i++) {
                uint32_t u[4]; cvt4(u, ra[i]);
                *(uint4*)&As[ar[i] * LDA + ac] = *(uint4*)u;
            }
#pragma unroll
            for (int i = 0; i < 2; i++) {
                uint32_t u[4]; cvt4(u, rb[i]);
                *(uint4*)&Bs[br_[i] * LDB + bc] = *(uint4*)u;
            }
        }
    }

#pragma unroll
    for (int i = 0; i < 2; i++) {
        const int r0 = m0 + wm * 32 + i * 16 + g;
#pragma unroll
        for (int j = 0; j < 4; j++) {
            const int cb = ncol + wn * 32 + j * 8 + 2 * t;
            const float* c = acc[i][j];
#pragma unroll
            for (int half = 0; half < 2; half++) {
                const int row = r0 + half * 8;
                float v0 = c[half * 2 + 0], v1 = c[half * 2 + 1];
                if (MODE == 0) {
                    if (bn < 4) {
                        *(float2*)&g_q[(size_t)row * 256 + cb] = make_float2(
                            __uint_as_float(f2tf(v0 * SCALE_Q)),
                            __uint_as_float(f2tf(v1 * SCALE_Q)));
                    } else {
                        float s0 = 1.0f / (1.0f + __expf(-(v0 + bvec[cb])));
                        float s1 = 1.0f / (1.0f + __expf(-(v1 + bvec[cb + 1])));
                        *(float2*)&g_gate[(size_t)row * 256 + cb] = make_float2(s0, s1);
                    }
                } else if (MODE == 1) {
                    float* dst = (bn < 4) ? g_k : g_v;
                    *(float2*)&dst[(size_t)row * 256 + cb] = make_float2(
                        __uint_as_float(f2tf(v0)), __uint_as_float(f2tf(v1)));
                } else {
                    *(float2*)&Dout[(size_t)row * 256 + cb] =
                        make_float2(v0 + bvec[cb], v1 + bvec[cb + 1]);
                }
            }
        }
    }
}

// ---------------- flash attention, warp-private q-rows ------------------------
// grid (Q/128, H, B), 256 thr (8 warps). Warp w owns q-rows w*16..w*16+15 and
// the FULL key range -> softmax reductions are intra-quad shuffles only.
#define ALD 36
#define VLD 40
#define OFF_Q    0
#define OFF_K    (OFF_Q + 128 * ALD)
#define OFF_V    (OFF_K + 2 * 64 * ALD)
#define ATTN_WORDS (OFF_V + 2 * 64 * VLD)
#define ATTN_BYTES (ATTN_WORDS * 4)

__device__ __forceinline__ void issue_kv(uint32_t smem_u32, const float* kbase,
                                         const float* vbase, int kc, int tid) {
    const int st = kc & 1;
#pragma unroll
    for (int i = 0; i < 2; i++) {
        int v = i * 256 + tid;
        int r = v >> 3, c4 = (v & 7) * 4;
        const size_t goff = (size_t)(kc * 64 + r) * C_ + c4;
        cp16(smem_u32 + (OFF_K + st * 64 * ALD + r * ALD + c4) * 4, kbase + goff);
        cp16(smem_u32 + (OFF_V + st * 64 * VLD + r * VLD + c4) * 4, vbase + goff);
    }
}

__global__ void __launch_bounds__(256) attn_flash(const float* __restrict__ bias,
                                                  const float* __restrict__ nbb) {
    extern __shared__ uint32_t sm[];
    uint32_t* qsm = sm + OFF_Q;

    const int tid = threadIdx.x;
    const int q0  = blockIdx.x * 128;
    const int h   = blockIdx.y;
    const int b   = blockIdx.z;
    const int warp = tid >> 5, lane = tid & 31;
    const int g = lane >> 2, t = lane & 3;

    const float* qbase = g_q + ((size_t)(b * Q_ + q0)) * C_ + h * HD_;
    const float* kbase = g_k + ((size_t)b * KK_) * C_ + h * HD_;
    const float* vbase = g_v + ((size_t)b * KK_) * C_ + h * HD_;
    const uint32_t smem_u32 = (uint32_t)__cvta_generic_to_shared(sm);

    // load q tile 128x32 (pre-rounded tf32; 4 float4/thread)
#pragma unroll
    for (int i = 0; i < 4; i++) {
        int v = i * 256 + tid;
        int r = v >> 3, c4 = (v & 7) * 4;
        *(float4*)&qsm[r * ALD + c4] = *(const float4*)(qbase + (size_t)r * C_ + c4);
    }
    issue_kv(smem_u32, kbase, vbase, 0, tid); CP_COMMIT();
    issue_kv(smem_u32, kbase, vbase, 1, tid); CP_COMMIT();
    __syncthreads();

    // q fragments -> registers (rows warp*16 + ...)
    uint32_t af[4][4];
#pragma unroll
    for (int k = 0; k < 4; k++) {
        af[k][0] = qsm[(warp * 16 + g) * ALD + k * 8 + t];
        af[k][1] = qsm[(warp * 16 + g + 8) * ALD + k * 8 + t];
        af[k][2] = qsm[(warp * 16 + g) * ALD + k * 8 + t + 4];
        af[k][3] = qsm[(warp * 16 + g + 8) * ALD + k * 8 + t + 4];
    }

    const int r0 = warp * 16 + g, r1 = r0 + 8;
    const float* brow0 = bias + ((size_t)(b * Q_ + q0 + r0)) * KK_;
    const float* brow1 = bias + ((size_t)(b * Q_ + q0 + r1)) * KK_;
    const float* nrow0 = nbb + ((size_t)(h * Q_ + q0 + r0)) * KK_;
    const float* nrow1 = nbb + ((size_t)(h * Q_ + q0 + r1)) * KK_;

    float rm0 = -1e30f, rm1 = -1e30f;
    float rs0 = 0.0f, rs1 = 0.0f;
    float o[4][4];
#pragma unroll
    for (int nf = 0; nf < 4; nf++)
#pragma unroll
        for (int c = 0; c < 4; c++) o[nf][c] = 0.0f;

    for (int kc = 0; kc < 8; kc++) {
        const int st = kc & 1;
        const uint32_t* Kb = sm + OFF_K + st * 64 * ALD;
        const uint32_t* Vb = sm + OFF_V + st * 64 * VLD;
        CP_WAIT1();
        __syncthreads();

        // ---- S = q k^T : warp's 16 rows x 64 keys ----
        float s[8][4];
#pragma unroll
        for (int j = 0; j < 8; j++)
#pragma unroll
            for (int c = 0; c < 4; c++) s[j][c] = 0.0f;
#pragma unroll
        for (int k = 0; k < 4; k++) {
            const int k8 = k * 8;
#pragma unroll
            for (int j = 0; j < 8; j++) {
                uint32_t bf[2];
                bf[0] = Kb[(j * 8 + g) * ALD + k8 + t];
                bf[1] = Kb[(j * 8 + g) * ALD + k8 + t + 4];
                mma8(s[j], af[k], bf);
            }
        }

        // ---- bias + nbb, row max ----
        float m0v = -1e30f, m1v = -1e30f;
#pragma unroll
        for (int j = 0; j < 8; j++) {
            const int col = kc * 64 + j * 8 + 2 * t;
            float2 b0 = *(const float2*)(brow0 + col);
            float2 n0 = *(const float2*)(nrow0 + col);
            float2 b1 = *(const float2*)(brow1 + col);
            float2 n1 = *(const float2*)(nrow1 + col);
            s[j][0] += b0.x + n0.x; s[j][1] += b0.y + n0.y;
            s[j][2] += b1.x + n1.x; s[j][3] += b1.y + n1.y;
            m0v = fmaxf(m0v, fmaxf(s[j][0], s[j][1]));
            m1v = fmaxf(m1v, fmaxf(s[j][2], s[j][3]));
        }
        m0v = fmaxf(m0v, __shfl_xor_sync(0xffffffff, m0v, 1));
        m0v = fmaxf(m0v, __shfl_xor_sync(0xffffffff, m0v, 2));
        m1v = fmaxf(m1v, __shfl_xor_sync(0xffffffff, m1v, 1));
        m1v = fmaxf(m1v, __shfl_xor_sync(0xffffffff, m1v, 2));
        const float nm0 = fmaxf(rm0, m0v), nm1 = fmaxf(rm1, m1v);
        const float c0 = __expf(rm0 - nm0), c1 = __expf(rm1 - nm1);
        rm0 = nm0; rm1 = nm1;

        // ---- exp + partial sums ----
        float sum0 = 0.0f, sum1 = 0.0f;
#pragma unroll
        for (int j = 0; j < 8; j++) {
            s[j][0] = __expf(s[j][0] - nm0); s[j][1] = __expf(s[j][1] - nm0);
            s[j][2] = __expf(s[j][2] - nm1); s[j][3] = __expf(s[j][3] - nm1);
            sum0 += s[j][0] + s[j][1];
            sum1 += s[j][2] + s[j][3];
        }
        sum0 += __shfl_xor_sync(0xffffffff, sum0, 1);
        sum0 += __shfl_xor_sync(0xffffffff, sum0, 2);
        sum1 += __shfl_xor_sync(0xffffffff, sum1, 1);
        sum1 += __shfl_xor_sync(0xffffffff, sum1, 2);
        rs0 = rs0 * c0 + sum0;
        rs1 = rs1 * c1 + sum1;

#pragma unroll
        for (int nf = 0; nf < 4; nf++) {
            o[nf][0] *= c0; o[nf][1] *= c0;
            o[nf][2] *= c1; o[nf][3] *= c1;
        }

        // ---- PV: rearrange P (C-frag) -> A-frag via quad shuffles ----
#pragma unroll
        for (int j = 0; j < 8; j++) {
            const int srcA = (lane & ~3) | (t >> 1);
            const int srcB = (lane & ~3) | 2 | (t >> 1);
            float v00 = __shfl_sync(0xffffffff, s[j][0], srcA);
            float v01 = __shfl_sync(0xffffffff, s[j][1], srcA);
            float v20 = __shfl_sync(0xffffffff, s[j][2], srcA);
            float v21 = __shfl_sync(0xffffffff, s[j][3], srcA);
            float w00 = __shfl_sync(0xffffffff, s[j][0], srcB);
            float w01 = __shfl_sync(0xffffffff, s[j][1], srcB);
            float w20 = __shfl_sync(0xffffffff, s[j][2], srcB);
            float w21 = __shfl_sync(0xffffffff, s[j][3], srcB);
            uint32_t pa[4];
            pa[0] = f2tf((t & 1) ? v01 : v00);
            pa[1] = f2tf((t & 1) ? v21 : v20);
            pa[2] = f2tf((t & 1) ? w01 : w00);
            pa[3] = f2tf((t & 1) ? w21 : w20);
            const int krow = j * 8;
#pragma unroll
            for (int nf = 0; nf < 4; nf++) {
                uint32_t bf[2];
                bf[0] = Vb[(krow + t) * VLD + nf * 8 + g];
                bf[1] = Vb[(krow + t + 4) * VLD + nf * 8 + g];
                mma8(o[nf], pa, bf);
            }
        }
        __syncthreads();
        if (kc + 2 < 8) issue_kv(smem_u32, kbase, vbase, kc + 2, tid);
        CP_COMMIT();
    }

    // ---- normalize, gate, store (warp-private, no combine) ----
    const float inv0 = 1.0f / rs0, inv1 = 1.0f / rs1;
#pragma unroll
    for (int half = 0; half < 2; half++) {
        const int r = half ? r1 : r0;
        const float inv = half ? inv1 : inv0;
        const size_t obase = ((size_t)(b * Q_ + q0 + r)) * C_ + h * HD_;
#pragma unroll
        for (int nf = 0; nf < 4; nf++) {
            const int d = nf * 8 + 2 * t;
            float2 ga = *(const float2*)&g_gate[obase + d];
            *(float2*)&g_wa[obase + d] = make_float2(
                o[nf][half * 2] * inv * ga.x,
                o[nf][half * 2 + 1] * inv * ga.y);
        }
    }
}

// ---------------- launch ------------------------------------------------------
extern "C" void kernel_launch(void* const* d_in, const int* in_sizes, int n_in,
                              void* d_out, int out_size) {
    const float* q_data    = (const float*)d_in[0];
    const float* m_data    = (const float*)d_in[1];
    const float* bias      = (const float*)d_in[2];
    const float* nbb       = (const float*)d_in[3];
    const float* query_w   = (const float*)d_in[4];
    const float* key_w     = (const float*)d_in[5];
    const float* value_w   = (const float*)d_in[6];
    const float* gating_w  = (const float*)d_in[7];
    const float* gating_b  = (const float*)d_in[8];
    const float* output_w  = (const float*)d_in[9];
    const float* output_b  = (const float*)d_in[10];
    float* out = (float*)d_out;

    cudaFuncSetAttribute(attn_flash, cudaFuncAttributeMaxDynamicSharedMemorySize,
                         ATTN_BYTES);

    proj_tc<0><<<dim3(256, 8), 256>>>(q_data, query_w, gating_w, gating_b, nullptr);
    proj_tc<1><<<dim3(256, 8), 256>>>(m_data, key_w, value_w, nullptr, nullptr);
    attn_flash<<<dim3(Q_ / 128, H_, B_), 256, ATTN_BYTES>>>(bias, nbb);
    proj_tc<2><<<dim3(256, 4), 256>>>(nullptr, output_w, nullptr, output_b, out);
}

// round 10
// speedup vs baseline: 1.3433x; 1.3433x over previous
#include <cuda_runtime.h>
#include <cuda_fp16.h>
#include <math.h>
#include <stdint.h>

#define B_   64
#define Q_   512
#define KK_  512
#define C_   256
#define H_   8
#define HD_  32
#define OUT_ 256
#define SCALE_Q 0.17677669529663687f   // 1/sqrt(32)

// ---------------- scratch (static device globals; no allocation) -------------
__device__ __align__(16) __half g_q16[B_ * Q_ * C_];   // fp16 scaled q  [b,q,hd]
__device__ __align__(16) __half g_k16[B_ * KK_ * C_];  // fp16 k         [b,k,hd]
__device__ __align__(16) __half g_vT16[B_ * C_ * KK_]; // fp16 v TRANSPOSED [b,hd,k]
__device__ __align__(16) float g_gate[B_ * Q_ * C_];   // sigmoid gate (fp32)
__device__ __align__(16) float g_wa[B_ * Q_ * C_];     // gated weighted avg (fp32)

// ---------------- helpers ------------------------------------------------------
__device__ __forceinline__ uint32_t f2tf(float x) {
    uint32_t u;
    asm("cvt.rna.tf32.f32 %0, %1;" : "=r"(u) : "f"(x));
    return u;
}
__device__ __forceinline__ void cvt4(uint32_t* d, float4 v) {
    d[0] = f2tf(v.x); d[1] = f2tf(v.y); d[2] = f2tf(v.z); d[3] = f2tf(v.w);
}
__device__ __forceinline__ void mma8(float* d, const uint32_t* a, const uint32_t* b) {
    asm volatile(
        "mma.sync.aligned.m16n8k8.row.col.f32.tf32.tf32.f32 "
        "{%0,%1,%2,%3}, {%4,%5,%6,%7}, {%8,%9}, {%0,%1,%2,%3};"
        : "+f"(d[0]), "+f"(d[1]), "+f"(d[2]), "+f"(d[3])
        : "r"(a[0]), "r"(a[1]), "r"(a[2]), "r"(a[3]), "r"(b[0]), "r"(b[1]));
}
__device__ __forceinline__ void mma16(float* d, const uint32_t* a,
                                      uint32_t b0, uint32_t b1) {
    asm volatile(
        "mma.sync.aligned.m16n8k16.row.col.f32.f16.f16.f32 "
        "{%0,%1,%2,%3}, {%4,%5,%6,%7}, {%8,%9}, {%0,%1,%2,%3};"
        : "+f"(d[0]), "+f"(d[1]), "+f"(d[2]), "+f"(d[3])
        : "r"(a[0]), "r"(a[1]), "r"(a[2]), "r"(a[3]), "r"(b0), "r"(b1));
}
__device__ __forceinline__ uint32_t packh2(float lo, float hi) {
    __half2 h = __floats2half2_rn(lo, hi);
    return *reinterpret_cast<uint32_t*>(&h);
}
__device__ __forceinline__ void cp16(uint32_t dst, const void* src) {
    asm volatile("cp.async.ca.shared.global [%0], [%1], 16;" :: "r"(dst), "l"(src));
}
#define CP_COMMIT() asm volatile("cp.async.commit_group;")
#define CP_WAIT1()  asm volatile("cp.async.wait_group 1;")

// ---------------- tf32 projection GEMM, register-prefetch pipeline -----------
#define LDA 36
#define LDB 72
template <int MODE>
__global__ void __launch_bounds__(256) proj_tc(const float* __restrict__ A,
                                               const float* __restrict__ W0,
                                               const float* __restrict__ W1,
                                               const float* __restrict__ bvec,
                                               float* __restrict__ Dout) {
    __shared__ uint32_t As[128 * LDA];
    __shared__ uint32_t Bs[32 * LDB];

    const int tid  = threadIdx.x;
    const int m0   = blockIdx.x * 128;
    const int bn   = blockIdx.y;
    const int warp = tid >> 5, lane = tid & 31;
    const int g = lane >> 2, t = lane & 3;
    const int wm = warp >> 1, wn = warp & 1;

    const float* Ap = (MODE == 2) ? g_wa : A;
    const float* W  = (MODE == 2) ? W0 : (bn < 4 ? W0 : W1);
    const int ncol  = (MODE == 2) ? bn * 64 : (bn & 3) * 64;

    const int ar[4] = {tid >> 3, (256 + tid) >> 3, (512 + tid) >> 3, (768 + tid) >> 3};
    const int ac = (tid & 7) * 4;
    const int br_[2] = {tid >> 4, (256 + tid) >> 4};
    const int bc = (tid & 15) * 4;

    float acc[2][4][4];
#pragma unroll
    for (int i = 0; i < 2; i++)
#pragma unroll
        for (int j = 0; j < 4; j++)
#pragma unroll
            for (int c = 0; c < 4; c++) acc[i][j][c] = 0.0f;

    float4 ra[4], rb[2];
#pragma unroll
    for (int i = 0; i < 4; i++)
        ra[i] = *(const float4*)(Ap + (size_t)(m0 + ar[i]) * 256 + ac);
#pragma unroll
    for (int i = 0; i < 2; i++)
        rb[i] = *(const float4*)(W + (size_t)br_[i] * 256 + ncol + bc);
#pragma unroll
    for (int i = 0; i < 4; i++) {
        uint32_t u[4]; cvt4(u, ra[i]);
        *(uint4*)&As[ar[i] * LDA + ac] = *(uint4*)u;
    }
#pragma unroll
    for (int i = 0; i < 2; i++) {
        uint32_t u[4]; cvt4(u, rb[i]);
        *(uint4*)&Bs[br_[i] * LDB + bc] = *(uint4*)u;
    }

    for (int it = 0; it < 8; it++) {
        __syncthreads();
        if (it < 7) {
            const int k0 = (it + 1) * 32;
#pragma unroll
            for (int i = 0; i < 4; i++)
                ra[i] = *(const float4*)(Ap + (size_t)(m0 + ar[i]) * 256 + k0 + ac);
#pragma unroll
            for (int i = 0; i < 2; i++)
                rb[i] = *(const float4*)(W + (size_t)(k0 + br_[i]) * 256 + ncol + bc);
        }

#pragma unroll
        for (int kk = 0; kk < 4; kk++) {
            const int k8 = kk * 8;
            uint32_t af[2][4], bf[4][2];
#pragma unroll
            for (int i = 0; i < 2; i++) {
                const int rb2 = wm * 32 + i * 16;
                af[i][0] = As[(rb2 + g) * LDA + k8 + t];
                af[i][1] = As[(rb2 + g + 8) * LDA + k8 + t];
                af[i][2] = As[(rb2 + g) * LDA + k8 + t + 4];
                af[i][3] = As[(rb2 + g + 8) * LDA + k8 + t + 4];
            }
#pragma unroll
            for (int j = 0; j < 4; j++) {
                const int nb = wn * 32 + j * 8;
                bf[j][0] = Bs[(k8 + t) * LDB + nb + g];
                bf[j][1] = Bs[(k8 + t + 4) * LDB + nb + g];
            }
#pragma unroll
            for (int i = 0; i < 2; i++)
#pragma unroll
                for (int j = 0; j < 4; j++) mma8(acc[i][j], af[i], bf[j]);
        }
        __syncthreads();
        if (it < 7) {
#pragma unroll
            for (int i = 0; i < 4; i++) {
                uint32_t u[4]; cvt4(u, ra[i]);
                *(uint4*)&As[ar[i] * LDA + ac] = *(uint4*)u;
            }
#pragma unroll
            for (int i = 0; i < 2; i++) {
                uint32_t u[4]; cvt4(u, rb[i]);
                *(uint4*)&Bs[br_[i] * LDB + bc] = *(uint4*)u;
            }
        }
    }

#pragma unroll
    for (int i = 0; i < 2; i++) {
        const int r0 = m0 + wm * 32 + i * 16 + g;
#pragma unroll
        for (int j = 0; j < 4; j++) {
            const int cb = ncol + wn * 32 + j * 8 + 2 * t;
            const float* c = acc[i][j];
#pragma unroll
            for (int half = 0; half < 2; half++) {
                const int row = r0 + half * 8;
                float v0 = c[half * 2 + 0], v1 = c[half * 2 + 1];
                if (MODE == 0) {
                    if (bn < 4) {
                        __half2 h = __floats2half2_rn(v0 * SCALE_Q, v1 * SCALE_Q);
                        *(__half2*)&g_q16[(size_t)row * 256 + cb] = h;
                    } else {
                        float s0 = 1.0f / (1.0f + __expf(-(v0 + bvec[cb])));
                        float s1 = 1.0f / (1.0f + __expf(-(v1 + bvec[cb + 1])));
                        *(float2*)&g_gate[(size_t)row * 256 + cb] = make_float2(s0, s1);
                    }
                } else if (MODE == 1) {
                    if (bn < 4) {
                        __half2 h = __floats2half2_rn(v0, v1);
                        *(__half2*)&g_k16[(size_t)row * 256 + cb] = h;
                    } else {
                        // V transposed: [b][hd][k], row = b*512 + k
                        const size_t bb = row >> 9, k = row & 511;
                        g_vT16[(bb * 256 + cb) * 512 + k]     = __float2half_rn(v0);
                        g_vT16[(bb * 256 + cb + 1) * 512 + k] = __float2half_rn(v1);
                    }
                } else {
                    *(float2*)&Dout[(size_t)row * 256 + cb] =
                        make_float2(v0 + bvec[cb], v1 + bvec[cb + 1]);
                }
            }
        }
    }
}

// ---------------- fp16 flash attention, shuffle-free PV -----------------------
// grid (Q/128, H, B), 256 thr (8 warps). Warp w owns q-rows w*16..w*16+15.
// Static smem: Q half2[128][20], K half2[2][64][20], Vt half2[2][32][36].
#define QS2 20
#define KS2 20
#define VS2 36
#define SQ_OFF  0
#define SK_OFF  (SQ_OFF + 128 * QS2)
#define SV_OFF  (SK_OFF + 2 * 64 * KS2)
#define SM_WORDS (SV_OFF + 2 * 32 * VS2)   // 7424 words = 29696 B

__global__ void __launch_bounds__(256) attn_flash(const float* __restrict__ bias,
                                                  const float* __restrict__ nbb) {
    __shared__ uint32_t sm[SM_WORDS];
    uint32_t* qsm2 = sm + SQ_OFF;

    const int tid = threadIdx.x;
    const int q0  = blockIdx.x * 128;
    const int h   = blockIdx.y;
    const int b   = blockIdx.z;
    const int warp = tid >> 5, lane = tid & 31;
    const int g = lane >> 2, t = lane & 3;

    const __half* qb  = g_q16 + ((size_t)(b * Q_ + q0)) * C_ + h * HD_;
    const __half* kb  = g_k16 + ((size_t)b * KK_) * C_ + h * HD_;
    const __half* vtb = g_vT16 + ((size_t)(b * 256 + h * HD_)) * KK_;
    const uint32_t smu = (uint32_t)__cvta_generic_to_shared(sm);

    // ---- Q tile 128x32 halves: 2 x 16B per thread ----
#pragma unroll
    for (int i = 0; i < 2; i++) {
        int v = i * 256 + tid;
        int r = v >> 2, seg = v & 3;
        uint4 d4 = *(const uint4*)(qb + (size_t)r * C_ + seg * 8);
        *(uint4*)&qsm2[r * QS2 + seg * 4] = d4;
    }

    // ---- K/Vt chunk copy: 1 cp16 each per thread ----
    auto issue_kv = [&](int kc) {
        const int st = kc & 1;
        {   // K: 64 rows x 32 halves (4 segs/row)
            int r = tid >> 2, seg = tid & 3;
            cp16(smu + (SK_OFF + st * 64 * KS2 + r * KS2 + seg * 4) * 4,
                 kb + (size_t)(kc * 64 + r) * C_ + seg * 8);
        }
        {   // Vt: 32 d-rows x 64 halves (8 segs/row)
            int d = tid >> 3, seg = tid & 7;
            cp16(smu + (SV_OFF + st * 32 * VS2 + d * VS2 + seg * 4) * 4,
                 vtb + (size_t)d * KK_ + kc * 64 + seg * 8);
        }
    };

    issue_kv(0); CP_COMMIT();
    issue_kv(1); CP_COMMIT();
    __syncthreads();

    // ---- Q fragments (m16n8k16, 2 k-groups) ----
    uint32_t af[2][4];
#pragma unroll
    for (int u = 0; u < 2; u++) {
        af[u][0] = qsm2[(warp * 16 + g) * QS2 + u * 8 + t];
        af[u][1] = qsm2[(warp * 16 + g + 8) * QS2 + u * 8 + t];
        af[u][2] = qsm2[(warp * 16 + g) * QS2 + u * 8 + t + 4];
        af[u][3] = qsm2[(warp * 16 + g + 8) * QS2 + u * 8 + t + 4];
    }

    const int r0 = warp * 16 + g, r1 = r0 + 8;
    const float* brow0 = bias + ((size_t)(b * Q_ + q0 + r0)) * KK_;
    const float* brow1 = bias + ((size_t)(b * Q_ + q0 + r1)) * KK_;
    const float* nrow0 = nbb + ((size_t)(h * Q_ + q0 + r0)) * KK_;
    const float* nrow1 = nbb + ((size_t)(h * Q_ + q0 + r1)) * KK_;

    float rm0 = -1e30f, rm1 = -1e30f;
    float rs0 = 0.0f, rs1 = 0.0f;
    float o[4][4];
#pragma unroll
    for (int nf = 0; nf < 4; nf++)
#pragma unroll
        for (int c = 0; c < 4; c++) o[nf][c] = 0.0f;

    for (int kc = 0; kc < 8; kc++) {
        const int st = kc & 1;
        const uint32_t* Kb2 = sm + SK_OFF + st * 64 * KS2;
        const uint32_t* Vb2 = sm + SV_OFF + st * 32 * VS2;
        CP_WAIT1();
        __syncthreads();

        // ---- S = q k^T : 16 rows x 64 keys, fp16 k16 mma ----
        float s[8][4];
#pragma unroll
        for (int j = 0; j < 8; j++)
#pragma unroll
            for (int c = 0; c < 4; c++) s[j][c] = 0.0f;
#pragma unroll
        for (int u = 0; u < 2; u++)
#pragma unroll
            for (int j = 0; j < 8; j++) {
                uint32_t b0 = Kb2[(j * 8 + g) * KS2 + u * 8 + t];
                uint32_t b1 = Kb2[(j * 8 + g) * KS2 + u * 8 + t + 4];
                mma16(s[j], af[u], b0, b1);
            }

        // ---- bias + nbb, row max ----
        float m0v = -1e30f, m1v = -1e30f;
#pragma unroll
        for (int j = 0; j < 8; j++) {
            const int col = kc * 64 + j * 8 + 2 * t;
            float2 b0 = *(const float2*)(brow0 + col);
            float2 n0 = *(const float2*)(nrow0 + col);
            float2 b1 = *(const float2*)(brow1 + col);
            float2 n1 = *(const float2*)(nrow1 + col);
            s[j][0] += b0.x + n0.x; s[j][1] += b0.y + n0.y;
            s[j][2] += b1.x + n1.x; s[j][3] += b1.y + n1.y;
            m0v = fmaxf(m0v, fmaxf(s[j][0], s[j][1]));
            m1v = fmaxf(m1v, fmaxf(s[j][2], s[j][3]));
        }
        m0v = fmaxf(m0v, __shfl_xor_sync(0xffffffff, m0v, 1));
        m0v = fmaxf(m0v, __shfl_xor_sync(0xffffffff, m0v, 2));
        m1v = fmaxf(m1v, __shfl_xor_sync(0xffffffff, m1v, 1));
        m1v = fmaxf(m1v, __shfl_xor_sync(0xffffffff, m1v, 2));
        const float nm0 = fmaxf(rm0, m0v), nm1 = fmaxf(rm1, m1v);
        const float c0 = __expf(rm0 - nm0), c1 = __expf(rm1 - nm1);
        rm0 = nm0; rm1 = nm1;

        // ---- exp + partial sums ----
        float sum0 = 0.0f, sum1 = 0.0f;
#pragma unroll
        for (int j = 0; j < 8; j++) {
            s[j][0] = __expf(s[j][0] - nm0); s[j][1] = __expf(s[j][1] - nm0);
            s[j][2] = __expf(s[j][2] - nm1); s[j][3] = __expf(s[j][3] - nm1);
            sum0 += s[j][0] + s[j][1];
            sum1 += s[j][2] + s[j][3];
        }
        sum0 += __shfl_xor_sync(0xffffffff, sum0, 1);
        sum0 += __shfl_xor_sync(0xffffffff, sum0, 2);
        sum1 += __shfl_xor_sync(0xffffffff, sum1, 1);
        sum1 += __shfl_xor_sync(0xffffffff, sum1, 2);
        rs0 = rs0 * c0 + sum0;
        rs1 = rs1 * c1 + sum1;

#pragma unroll
        for (int nf = 0; nf < 4; nf++) {
            o[nf][0] *= c0; o[nf][1] *= c0;
            o[nf][2] *= c1; o[nf][3] *= c1;
        }

        // ---- PV: P C-frag == fp16 A-frag, zero shuffles ----
#pragma unroll
        for (int u = 0; u < 4; u++) {
            uint32_t pa[4];
            pa[0] = packh2(s[2 * u][0], s[2 * u][1]);
            pa[1] = packh2(s[2 * u][2], s[2 * u][3]);
            pa[2] = packh2(s[2 * u + 1][0], s[2 * u + 1][1]);
            pa[3] = packh2(s[2 * u + 1][2], s[2 * u + 1][3]);
#pragma unroll
            for (int nf = 0; nf < 4; nf++) {
                uint32_t b0 = Vb2[(nf * 8 + g) * VS2 + u * 8 + t];
                uint32_t b1 = Vb2[(nf * 8 + g) * VS2 + u * 8 + t + 4];
                mma16(o[nf], pa, b0, b1);
            }
        }
        __syncthreads();
        if (kc + 2 < 8) issue_kv(kc + 2);
        CP_COMMIT();
    }

    // ---- normalize, gate, store ----
    const float inv0 = 1.0f / rs0, inv1 = 1.0f / rs1;
#pragma unroll
    for (int half = 0; half < 2; half++) {
        const int r = half ? r1 : r0;
        const float inv = half ? inv1 : inv0;
        const size_t obase = ((size_t)(b * Q_ + q0 + r)) * C_ + h * HD_;
#pragma unroll
        for (int nf = 0; nf < 4; nf++) {
            const int d = nf * 8 + 2 * t;
            float2 ga = *(const float2*)&g_gate[obase + d];
            *(float2*)&g_wa[obase + d] = make_float2(
                o[nf][half * 2] * inv * ga.x,
                o[nf][half * 2 + 1] * inv * ga.y);
        }
    }
}

// ---------------- launch ------------------------------------------------------
extern "C" void kernel_launch(void* const* d_in, const int* in_sizes, int n_in,
                              void* d_out, int out_size) {
    const float* q_data    = (const float*)d_in[0];
    const float* m_data    = (const float*)d_in[1];
    const float* bias      = (const float*)d_in[2];
    const float* nbb       = (const float*)d_in[3];
    const float* query_w   = (const float*)d_in[4];
    const float* key_w     = (const float*)d_in[5];
    const float* value_w   = (const float*)d_in[6];
    const float* gating_w  = (const float*)d_in[7];
    const float* gating_b  = (const float*)d_in[8];
    const float* output_w  = (const float*)d_in[9];
    const float* output_b  = (const float*)d_in[10];
    float* out = (float*)d_out;

    proj_tc<0><<<dim3(256, 8), 256>>>(q_data, query_w, gating_w, gating_b, nullptr);
    proj_tc<1><<<dim3(256, 8), 256>>>(m_data, key_w, value_w, nullptr, nullptr);
    attn_flash<<<dim3(Q_ / 128, H_, B_), 256>>>(bias, nbb);
    proj_tc<2><<<dim3(256, 4), 256>>>(nullptr, output_w, nullptr, output_b, out);
}

// round 11
// speedup vs baseline: 1.5331x; 1.1413x over previous
#include <cuda_runtime.h>
#include <cuda_fp16.h>
#include <math.h>
#include <stdint.h>

#define B_   64
#define Q_   512
#define KK_  512
#define C_   256
#define H_   8
#define HD_  32
#define OUT_ 256
#define SCALE_Q 0.17677669529663687f   // 1/sqrt(32)

// ---------------- scratch (static device globals; no allocation) -------------
__device__ __align__(16) __half g_q16[B_ * Q_ * C_];   // fp16 scaled q  [b,q,hd]
__device__ __align__(16) __half g_k16[B_ * KK_ * C_];  // fp16 k         [b,k,hd]
__device__ __align__(16) __half g_vT16[B_ * C_ * KK_]; // fp16 v transposed [b,hd,k]
__device__ __align__(16) __half g_wa16[B_ * Q_ * C_];  // fp16 gated weighted avg
__device__ __align__(16) float  g_gate[B_ * Q_ * C_];  // sigmoid gate (fp32)
__device__ __align__(16) __half g_w16T[5 * C_ * C_];   // fp16 weights transposed [m][n][k]

// ---------------- helpers ------------------------------------------------------
__device__ __forceinline__ void mma16(float* d, const uint32_t* a,
                                      uint32_t b0, uint32_t b1) {
    asm volatile(
        "mma.sync.aligned.m16n8k16.row.col.f32.f16.f16.f32 "
        "{%0,%1,%2,%3}, {%4,%5,%6,%7}, {%8,%9}, {%0,%1,%2,%3};"
        : "+f"(d[0]), "+f"(d[1]), "+f"(d[2]), "+f"(d[3])
        : "r"(a[0]), "r"(a[1]), "r"(a[2]), "r"(a[3]), "r"(b0), "r"(b1));
}
__device__ __forceinline__ uint32_t packh2(float lo, float hi) {
    __half2 h = __floats2half2_rn(lo, hi);
    return *reinterpret_cast<uint32_t*>(&h);
}
__device__ __forceinline__ void cp16(uint32_t dst, const void* src) {
    asm volatile("cp.async.ca.shared.global [%0], [%1], 16;" :: "r"(dst), "l"(src));
}
#define CP_COMMIT() asm volatile("cp.async.commit_group;")
#define CP_WAIT1()  asm volatile("cp.async.wait_group 1;")

// ---------------- weight prep: fp32 [k][n] -> fp16 transposed [n][k] ----------
__global__ void wprep(const float* __restrict__ qw, const float* __restrict__ kw,
                      const float* __restrict__ vw, const float* __restrict__ gw,
                      const float* __restrict__ ow) {
    const float* src[5] = {qw, kw, vw, gw, ow};
    const int m = blockIdx.y, k = blockIdx.x, n = threadIdx.x;
    g_w16T[(size_t)m * 65536 + n * 256 + k] = __float2half_rn(src[m][k * 256 + n]);
}

// ---------------- fp16 projection GEMM ----------------------------------------
// C[M,*] = A[M,256] x W[256,256], BM=128, BN=64, BK=32, 256 thr, m16n8k16.
// A: fp32 in-kernel converted (MODE 0/1) or fp16 g_wa16 (MODE 2).
// W: fp16 pre-transposed g_w16T.
#define PLDA 20
#define PLDB 20
template <int MODE>
__global__ void __launch_bounds__(256) proj16(const float* __restrict__ A,
                                              const float* __restrict__ bvec,
                                              float* __restrict__ Dout) {
    __shared__ uint32_t As2[128 * PLDA];   // [row][k-word]
    __shared__ uint32_t Bs2[64 * PLDB];    // [n][k-word]

    const int tid  = threadIdx.x;
    const int m0   = blockIdx.x * 128;
    const int bn   = blockIdx.y;
    const int warp = tid >> 5, lane = tid & 31;
    const int g = lane >> 2, t = lane & 3;
    const int wm = warp >> 1, wn = warp & 1;

    const int ncol = (MODE == 2) ? bn * 64 : (bn & 3) * 64;
    const int msel = (MODE == 0) ? (bn < 4 ? 0 : 3)
                   : (MODE == 1) ? (bn < 4 ? 1 : 2) : 4;
    const __half* Wt = g_w16T + (size_t)msel * 65536;

    // load coords
    const int ar[4] = {tid >> 3, (256 + tid) >> 3, (512 + tid) >> 3, (768 + tid) >> 3};
    const int ac = (tid & 7) * 4;                    // fp32 A path
    const int ar16[2] = {tid >> 2, (256 + tid) >> 2};
    const int aseg = tid & 3;                        // fp16 A path
    const int brn = tid >> 2, bseg = tid & 3;        // B path

    float acc[2][4][4];
#pragma unroll
    for (int i = 0; i < 2; i++)
#pragma unroll
        for (int j = 0; j < 4; j++)
#pragma unroll
            for (int c = 0; c < 4; c++) acc[i][j][c] = 0.0f;

    float4 ra[4];
    uint4  ra16[2];
    uint4  rbw;

    // prologue loads (k0 = 0)
    if (MODE == 2) {
#pragma unroll
        for (int i = 0; i < 2; i++)
            ra16[i] = *(const uint4*)(g_wa16 + (size_t)(m0 + ar16[i]) * 256 + aseg * 8);
    } else {
#pragma unroll
        for (int i = 0; i < 4; i++)
            ra[i] = *(const float4*)(A + (size_t)(m0 + ar[i]) * 256 + ac);
    }
    rbw = *(const uint4*)(Wt + (size_t)(ncol + brn) * 256 + bseg * 8);

    // prologue stores
    if (MODE == 2) {
#pragma unroll
        for (int i = 0; i < 2; i++)
            *(uint4*)&As2[ar16[i] * PLDA + aseg * 4] = ra16[i];
    } else {
#pragma unroll
        for (int i = 0; i < 4; i++) {
            uint2 u; u.x = packh2(ra[i].x, ra[i].y); u.y = packh2(ra[i].z, ra[i].w);
            *(uint2*)&As2[ar[i] * PLDA + (ac >> 1)] = u;
        }
    }
    *(uint4*)&Bs2[brn * PLDB + bseg * 4] = rbw;

    for (int it = 0; it < 8; it++) {
        __syncthreads();
        if (it < 7) {
            const int k0 = (it + 1) * 32;
            if (MODE == 2) {
#pragma unroll
                for (int i = 0; i < 2; i++)
                    ra16[i] = *(const uint4*)(g_wa16 +
                        (size_t)(m0 + ar16[i]) * 256 + k0 + aseg * 8);
            } else {
#pragma unroll
                for (int i = 0; i < 4; i++)
                    ra[i] = *(const float4*)(A + (size_t)(m0 + ar[i]) * 256 + k0 + ac);
            }
            rbw = *(const uint4*)(Wt + (size_t)(ncol + brn) * 256 + k0 + bseg * 8);
        }

#pragma unroll
        for (int u = 0; u < 2; u++) {
            uint32_t af[2][4], bf[4][2];
#pragma unroll
            for (int i = 0; i < 2; i++) {
                const int rb2 = wm * 32 + i * 16;
                af[i][0] = As2[(rb2 + g) * PLDA + u * 8 + t];
                af[i][1] = As2[(rb2 + g + 8) * PLDA + u * 8 + t];
                af[i][2] = As2[(rb2 + g) * PLDA + u * 8 + t + 4];
                af[i][3] = As2[(rb2 + g + 8) * PLDA + u * 8 + t + 4];
            }
#pragma unroll
            for (int j = 0; j < 4; j++) {
                const int nb = wn * 32 + j * 8;
                bf[j][0] = Bs2[(nb + g) * PLDB + u * 8 + t];
                bf[j][1] = Bs2[(nb + g) * PLDB + u * 8 + t + 4];
            }
#pragma unroll
            for (int i = 0; i < 2; i++)
#pragma unroll
                for (int j = 0; j < 4; j++) mma16(acc[i][j], af[i], bf[j][0], bf[j][1]);
        }
        __syncthreads();
        if (it < 7) {
            if (MODE == 2) {
#pragma unroll
                for (int i = 0; i < 2; i++)
                    *(uint4*)&As2[ar16[i] * PLDA + aseg * 4] = ra16[i];
            } else {
#pragma unroll
                for (int i = 0; i < 4; i++) {
                    uint2 u; u.x = packh2(ra[i].x, ra[i].y); u.y = packh2(ra[i].z, ra[i].w);
                    *(uint2*)&As2[ar[i] * PLDA + (ac >> 1)] = u;
                }
            }
            *(uint4*)&Bs2[brn * PLDB + bseg * 4] = rbw;
        }
    }

    // epilogue
#pragma unroll
    for (int i = 0; i < 2; i++) {
        const int r0 = m0 + wm * 32 + i * 16 + g;
#pragma unroll
        for (int j = 0; j < 4; j++) {
            const int cb = ncol + wn * 32 + j * 8 + 2 * t;
            const float* c = acc[i][j];
#pragma unroll
            for (int half = 0; half < 2; half++) {
                const int row = r0 + half * 8;
                float v0 = c[half * 2 + 0], v1 = c[half * 2 + 1];
                if (MODE == 0) {
                    if (bn < 4) {
                        *(__half2*)&g_q16[(size_t)row * 256 + cb] =
                            __floats2half2_rn(v0 * SCALE_Q, v1 * SCALE_Q);
                    } else {
                        float s0 = 1.0f / (1.0f + __expf(-(v0 + bvec[cb])));
                        float s1 = 1.0f / (1.0f + __expf(-(v1 + bvec[cb + 1])));
                        *(float2*)&g_gate[(size_t)row * 256 + cb] = make_float2(s0, s1);
                    }
                } else if (MODE == 1) {
                    if (bn < 4) {
                        *(__half2*)&g_k16[(size_t)row * 256 + cb] =
                            __floats2half2_rn(v0, v1);
                    } else {
                        // V transposed: [b][hd][k], row = b*512 + k
                        const size_t bb = row >> 9, k = row & 511;
                        g_vT16[(bb * 256 + cb) * 512 + k]     = __float2half_rn(v0);
                        g_vT16[(bb * 256 + cb + 1) * 512 + k] = __float2half_rn(v1);
                    }
                } else {
                    *(float2*)&Dout[(size_t)row * 256 + cb] =
                        make_float2(v0 + bvec[cb], v1 + bvec[cb + 1]);
                }
            }
        }
    }
}

// ---------------- fp16 flash attention, shuffle-free PV -----------------------
// grid (Q/128, H, B), 256 thr (8 warps). Warp w owns q-rows w*16..w*16+15.
#define QS2 20
#define KS2 20
#define VS2 36
#define SQ_OFF  0
#define SK_OFF  (SQ_OFF + 128 * QS2)
#define SV_OFF  (SK_OFF + 2 * 64 * KS2)
#define SM_WORDS (SV_OFF + 2 * 32 * VS2)   // 29696 B

__global__ void __launch_bounds__(256) attn_flash(const float* __restrict__ bias,
                                                  const float* __restrict__ nbb) {
    __shared__ uint32_t sm[SM_WORDS];
    uint32_t* qsm2 = sm + SQ_OFF;

    const int tid = threadIdx.x;
    const int q0  = blockIdx.x * 128;
    const int h   = blockIdx.y;
    const int b   = blockIdx.z;
    const int warp = tid >> 5, lane = tid & 31;
    const int g = lane >> 2, t = lane & 3;

    const __half* qb  = g_q16 + ((size_t)(b * Q_ + q0)) * C_ + h * HD_;
    const __half* kb  = g_k16 + ((size_t)b * KK_) * C_ + h * HD_;
    const __half* vtb = g_vT16 + ((size_t)(b * 256 + h * HD_)) * KK_;
    const uint32_t smu = (uint32_t)__cvta_generic_to_shared(sm);

    // ---- Q tile 128x32 halves ----
#pragma unroll
    for (int i = 0; i < 2; i++) {
        int v = i * 256 + tid;
        int r = v >> 2, seg = v & 3;
        uint4 d4 = *(const uint4*)(qb + (size_t)r * C_ + seg * 8);
        *(uint4*)&qsm2[r * QS2 + seg * 4] = d4;
    }

    auto issue_kv = [&](int kc) {
        const int st = kc & 1;
        {   int r = tid >> 2, seg = tid & 3;
            cp16(smu + (SK_OFF + st * 64 * KS2 + r * KS2 + seg * 4) * 4,
                 kb + (size_t)(kc * 64 + r) * C_ + seg * 8);
        }
        {   int d = tid >> 3, seg = tid & 7;
            cp16(smu + (SV_OFF + st * 32 * VS2 + d * VS2 + seg * 4) * 4,
                 vtb + (size_t)d * KK_ + kc * 64 + seg * 8);
        }
    };

    issue_kv(0); CP_COMMIT();
    issue_kv(1); CP_COMMIT();
    __syncthreads();

    uint32_t af[2][4];
#pragma unroll
    for (int u = 0; u < 2; u++) {
        af[u][0] = qsm2[(warp * 16 + g) * QS2 + u * 8 + t];
        af[u][1] = qsm2[(warp * 16 + g + 8) * QS2 + u * 8 + t];
        af[u][2] = qsm2[(warp * 16 + g) * QS2 + u * 8 + t + 4];
        af[u][3] = qsm2[(warp * 16 + g + 8) * QS2 + u * 8 + t + 4];
    }

    const int r0 = warp * 16 + g, r1 = r0 + 8;
    const float* brow0 = bias + ((size_t)(b * Q_ + q0 + r0)) * KK_;
    const float* brow1 = bias + ((size_t)(b * Q_ + q0 + r1)) * KK_;
    const float* nrow0 = nbb + ((size_t)(h * Q_ + q0 + r0)) * KK_;
    const float* nrow1 = nbb + ((size_t)(h * Q_ + q0 + r1)) * KK_;

    float rm0 = -1e30f, rm1 = -1e30f;
    float rs0 = 0.0f, rs1 = 0.0f;
    float o[4][4];
#pragma unroll
    for (int nf = 0; nf < 4; nf++)
#pragma unroll
        for (int c = 0; c < 4; c++) o[nf][c] = 0.0f;

    for (int kc = 0; kc < 8; kc++) {
        const int st = kc & 1;
        const uint32_t* Kb2 = sm + SK_OFF + st * 64 * KS2;
        const uint32_t* Vb2 = sm + SV_OFF + st * 32 * VS2;
        CP_WAIT1();
        __syncthreads();

        float s[8][4];
#pragma unroll
        for (int j = 0; j < 8; j++)
#pragma unroll
            for (int c = 0; c < 4; c++) s[j][c] = 0.0f;
#pragma unroll
        for (int u = 0; u < 2; u++)
#pragma unroll
            for (int j = 0; j < 8; j++) {
                uint32_t b0 = Kb2[(j * 8 + g) * KS2 + u * 8 + t];
                uint32_t b1 = Kb2[(j * 8 + g) * KS2 + u * 8 + t + 4];
                mma16(s[j], af[u], b0, b1);
            }

        float m0v = -1e30f, m1v = -1e30f;
#pragma unroll
        for (int j = 0; j < 8; j++) {
            const int col = kc * 64 + j * 8 + 2 * t;
            float2 b0 = *(const float2*)(brow0 + col);
            float2 n0 = *(const float2*)(nrow0 + col);
            float2 b1 = *(const float2*)(brow1 + col);
            float2 n1 = *(const float2*)(nrow1 + col);
            s[j][0] += b0.x + n0.x; s[j][1] += b0.y + n0.y;
            s[j][2] += b1.x + n1.x; s[j][3] += b1.y + n1.y;
            m0v = fmaxf(m0v, fmaxf(s[j][0], s[j][1]));
            m1v = fmaxf(m1v, fmaxf(s[j][2], s[j][3]));
        }
        m0v = fmaxf(m0v, __shfl_xor_sync(0xffffffff, m0v, 1));
        m0v = fmaxf(m0v, __shfl_xor_sync(0xffffffff, m0v, 2));
        m1v = fmaxf(m1v, __shfl_xor_sync(0xffffffff, m1v, 1));
        m1v = fmaxf(m1v, __shfl_xor_sync(0xffffffff, m1v, 2));
        const float nm0 = fmaxf(rm0, m0v), nm1 = fmaxf(rm1, m1v);
        const float c0 = __expf(rm0 - nm0), c1 = __expf(rm1 - nm1);
        rm0 = nm0; rm1 = nm1;

        float sum0 = 0.0f, sum1 = 0.0f;
#pragma unroll
        for (int j = 0; j < 8; j++) {
            s[j][0] = __expf(s[j][0] - nm0); s[j][1] = __expf(s[j][1] - nm0);
            s[j][2] = __expf(s[j][2] - nm1); s[j][3] = __expf(s[j][3] - nm1);
            sum0 += s[j][0] + s[j][1];
            sum1 += s[j][2] + s[j][3];
        }
        sum0 += __shfl_xor_sync(0xffffffff, sum0, 1);
        sum0 += __shfl_xor_sync(0xffffffff, sum0, 2);
        sum1 += __shfl_xor_sync(0xffffffff, sum1, 1);
        sum1 += __shfl_xor_sync(0xffffffff, sum1, 2);
        rs0 = rs0 * c0 + sum0;
        rs1 = rs1 * c1 + sum1;

#pragma unroll
        for (int nf = 0; nf < 4; nf++) {
            o[nf][0] *= c0; o[nf][1] *= c0;
            o[nf][2] *= c1; o[nf][3] *= c1;
        }

#pragma unroll
        for (int u = 0; u < 4; u++) {
            uint32_t pa[4];
            pa[0] = packh2(s[2 * u][0], s[2 * u][1]);
            pa[1] = packh2(s[2 * u][2], s[2 * u][3]);
            pa[2] = packh2(s[2 * u + 1][0], s[2 * u + 1][1]);
            pa[3] = packh2(s[2 * u + 1][2], s[2 * u + 1][3]);
#pragma unroll
            for (int nf = 0; nf < 4; nf++) {
                uint32_t b0 = Vb2[(nf * 8 + g) * VS2 + u * 8 + t];
                uint32_t b1 = Vb2[(nf * 8 + g) * VS2 + u * 8 + t + 4];
                mma16(o[nf], pa, b0, b1);
            }
        }
        __syncthreads();
        if (kc + 2 < 8) issue_kv(kc + 2);
        CP_COMMIT();
    }

    // ---- normalize, gate, store fp16 ----
    const float inv0 = 1.0f / rs0, inv1 = 1.0f / rs1;
#pragma unroll
    for (int half = 0; half < 2; half++) {
        const int r = half ? r1 : r0;
        const float inv = half ? inv1 : inv0;
        const size_t obase = ((size_t)(b * Q_ + q0 + r)) * C_ + h * HD_;
#pragma unroll
        for (int nf = 0; nf < 4; nf++) {
            const int d = nf * 8 + 2 * t;
            float2 ga = *(const float2*)&g_gate[obase + d];
            *(__half2*)&g_wa16[obase + d] = __floats2half2_rn(
                o[nf][half * 2] * inv * ga.x,
                o[nf][half * 2 + 1] * inv * ga.y);
        }
    }
}

// ---------------- launch ------------------------------------------------------
extern "C" void kernel_launch(void* const* d_in, const int* in_sizes, int n_in,
                              void* d_out, int out_size) {
    const float* q_data    = (const float*)d_in[0];
    const float* m_data    = (const float*)d_in[1];
    const float* bias      = (const float*)d_in[2];
    const float* nbb       = (const float*)d_in[3];
    const float* query_w   = (const float*)d_in[4];
    const float* key_w     = (const float*)d_in[5];
    const float* value_w   = (const float*)d_in[6];
    const float* gating_w  = (const float*)d_in[7];
    const float* gating_b  = (const float*)d_in[8];
    const float* output_w  = (const float*)d_in[9];
    const float* output_b  = (const float*)d_in[10];
    float* out = (float*)d_out;

    wprep<<<dim3(256, 5), 256>>>(query_w, key_w, value_w, gating_w, output_w);
    proj16<0><<<dim3(256, 8), 256>>>(q_data, gating_b, nullptr);
    proj16<1><<<dim3(256, 8), 256>>>(m_data, nullptr, nullptr);
    attn_flash<<<dim3(Q_ / 128, H_, B_), 256>>>(bias, nbb);
    proj16<2><<<dim3(256, 4), 256>>>(nullptr, output_b, out);
}

// round 14
// speedup vs baseline: 1.5655x; 1.0212x over previous
#include <cuda_runtime.h>
#include <cuda_fp16.h>
#include <math.h>
#include <stdint.h>

#define B_   64
#define Q_   512
#define KK_  512
#define C_   256
#define H_   8
#define HD_  32
#define OUT_ 256
#define SCALE_Q 0.17677669529663687f   // 1/sqrt(32)
#define SOFT_OFF 8.0f                  // fixed softmax offset (see analysis)

// ---------------- scratch (static device globals; no allocation) -------------
__device__ __align__(16) __half g_q16[B_ * Q_ * C_];   // fp16 scaled q  [b,q,hd]
__device__ __align__(16) __half g_k16[B_ * KK_ * C_];  // fp16 k         [b,k,hd]
__device__ __align__(16) __half g_vT16[B_ * C_ * KK_]; // fp16 v transposed [b,hd,k]
__device__ __align__(16) __half g_wa16[B_ * Q_ * C_];  // fp16 gated weighted avg
__device__ __align__(16) float  g_gate[B_ * Q_ * C_];  // sigmoid gate (fp32)
__device__ __align__(16) __half g_w16T[5 * C_ * C_];   // fp16 weights transposed [m][n][k]

// ---------------- helpers ------------------------------------------------------
__device__ __forceinline__ void mma16(float* d, const uint32_t* a,
                                      uint32_t b0, uint32_t b1) {
    asm volatile(
        "mma.sync.aligned.m16n8k16.row.col.f32.f16.f16.f32 "
        "{%0,%1,%2,%3}, {%4,%5,%6,%7}, {%8,%9}, {%0,%1,%2,%3};"
        : "+f"(d[0]), "+f"(d[1]), "+f"(d[2]), "+f"(d[3])
        : "r"(a[0]), "r"(a[1]), "r"(a[2]), "r"(a[3]), "r"(b0), "r"(b1));
}
__device__ __forceinline__ uint32_t packh2(float lo, float hi) {
    __half2 h = __floats2half2_rn(lo, hi);
    return *reinterpret_cast<uint32_t*>(&h);
}
__device__ __forceinline__ void cp16(uint32_t dst, const void* src) {
    asm volatile("cp.async.ca.shared.global [%0], [%1], 16;" :: "r"(dst), "l"(src));
}
#define CP_COMMIT() asm volatile("cp.async.commit_group;")
#define CP_WAIT1()  asm volatile("cp.async.wait_group 1;")

// ---------------- weight prep: fp32 [k][n] -> fp16 transposed [n][k] ----------
__global__ void wprep(const float* __restrict__ qw, const float* __restrict__ kw,
                      const float* __restrict__ vw, const float* __restrict__ gw,
                      const float* __restrict__ ow) {
    const float* src[5] = {qw, kw, vw, gw, ow};
    const int m = blockIdx.y, k = blockIdx.x, n = threadIdx.x;
    g_w16T[(size_t)m * 65536 + n * 256 + k] = __float2half_rn(src[m][k * 256 + n]);
}

// ---------------- fp16 projection GEMMs ---------------------------------------
// BM=128, BN=64, BK=32, 256 thr, m16n8k16; W from g_w16T (fp16, [n][k]).
#define PLDA 20
#define PLDB 20

// q/gate (z=0) and k/v (z=1) projections merged into one launch.
__global__ void __launch_bounds__(256) proj01(const float* __restrict__ Aq,
                                              const float* __restrict__ Am,
                                              const float* __restrict__ gbias) {
    __shared__ uint32_t As2[128 * PLDA];
    __shared__ uint32_t Bs2[64 * PLDB];

    const int tid  = threadIdx.x;
    const int m0   = blockIdx.x * 128;
    const int bn   = blockIdx.y;
    const int mode0 = (blockIdx.z == 0);
    const int warp = tid >> 5, lane = tid & 31;
    const int g = lane >> 2, t = lane & 3;
    const int wm = warp >> 1, wn = warp & 1;

    const float* A = mode0 ? Aq : Am;
    const int ncol = (bn & 3) * 64;
    const int msel = mode0 ? (bn < 4 ? 0 : 3) : (bn < 4 ? 1 : 2);
    const __half* Wt = g_w16T + (size_t)msel * 65536;

    const int ar[4] = {tid >> 3, (256 + tid) >> 3, (512 + tid) >> 3, (768 + tid) >> 3};
    const int ac = (tid & 7) * 4;
    const int brn = tid >> 2, bseg = tid & 3;

    float acc[2][4][4];
#pragma unroll
    for (int i = 0; i < 2; i++)
#pragma unroll
        for (int j = 0; j < 4; j++)
#pragma unroll
            for (int c = 0; c < 4; c++) acc[i][j][c] = 0.0f;

    float4 ra[4];
    uint4  rbw;
#pragma unroll
    for (int i = 0; i < 4; i++)
        ra[i] = *(const float4*)(A + (size_t)(m0 + ar[i]) * 256 + ac);
    rbw = *(const uint4*)(Wt + (size_t)(ncol + brn) * 256 + bseg * 8);
#pragma unroll
    for (int i = 0; i < 4; i++) {
        uint2 u; u.x = packh2(ra[i].x, ra[i].y); u.y = packh2(ra[i].z, ra[i].w);
        *(uint2*)&As2[ar[i] * PLDA + (ac >> 1)] = u;
    }
    *(uint4*)&Bs2[brn * PLDB + bseg * 4] = rbw;

    for (int it = 0; it < 8; it++) {
        __syncthreads();
        if (it < 7) {
            const int k0 = (it + 1) * 32;
#pragma unroll
            for (int i = 0; i < 4; i++)
                ra[i] = *(const float4*)(A + (size_t)(m0 + ar[i]) * 256 + k0 + ac);
            rbw = *(const uint4*)(Wt + (size_t)(ncol + brn) * 256 + k0 + bseg * 8);
        }
#pragma unroll
        for (int u = 0; u < 2; u++) {
            uint32_t af[2][4], bf[4][2];
#pragma unroll
            for (int i = 0; i < 2; i++) {
                const int rb2 = wm * 32 + i * 16;
                af[i][0] = As2[(rb2 + g) * PLDA + u * 8 + t];
                af[i][1] = As2[(rb2 + g + 8) * PLDA + u * 8 + t];
                af[i][2] = As2[(rb2 + g) * PLDA + u * 8 + t + 4];
                af[i][3] = As2[(rb2 + g + 8) * PLDA + u * 8 + t + 4];
            }
#pragma unroll
            for (int j = 0; j < 4; j++) {
                const int nb = wn * 32 + j * 8;
                bf[j][0] = Bs2[(nb + g) * PLDB + u * 8 + t];
                bf[j][1] = Bs2[(nb + g) * PLDB + u * 8 + t + 4];
            }
#pragma unroll
            for (int i = 0; i < 2; i++)
#pragma unroll
                for (int j = 0; j < 4; j++) mma16(acc[i][j], af[i], bf[j][0], bf[j][1]);
        }
        __syncthreads();
        if (it < 7) {
#pragma unroll
            for (int i = 0; i < 4; i++) {
                uint2 u; u.x = packh2(ra[i].x, ra[i].y); u.y = packh2(ra[i].z, ra[i].w);
                *(uint2*)&As2[ar[i] * PLDA + (ac >> 1)] = u;
            }
            *(uint4*)&Bs2[brn * PLDB + bseg * 4] = rbw;
        }
    }

#pragma unroll
    for (int i = 0; i < 2; i++) {
        const int r0 = m0 + wm * 32 + i * 16 + g;
#pragma unroll
        for (int j = 0; j < 4; j++) {
            const int cb = ncol + wn * 32 + j * 8 + 2 * t;
            const float* c = acc[i][j];
#pragma unroll
            for (int half = 0; half < 2; half++) {
                const int row = r0 + half * 8;
                float v0 = c[half * 2 + 0], v1 = c[half * 2 + 1];
                if (mode0) {
                    if (bn < 4) {
                        *(__half2*)&g_q16[(size_t)row * 256 + cb] =
                            __floats2half2_rn(v0 * SCALE_Q, v1 * SCALE_Q);
                    } else {
                        float s0 = 1.0f / (1.0f + __expf(-(v0 + gbias[cb])));
                        float s1 = 1.0f / (1.0f + __expf(-(v1 + gbias[cb + 1])));
                        *(float2*)&g_gate[(size_t)row * 256 + cb] = make_float2(s0, s1);
                    }
                } else {
                    if (bn < 4) {
                        *(__half2*)&g_k16[(size_t)row * 256 + cb] =
                            __floats2half2_rn(v0, v1);
                    } else {
                        const size_t bb = row >> 9, k = row & 511;
                        g_vT16[(bb * 256 + cb) * 512 + k]     = __float2half_rn(v0);
                        g_vT16[(bb * 256 + cb + 1) * 512 + k] = __float2half_rn(v1);
                    }
                }
            }
        }
    }
}

// output projection: fp16 A (g_wa16) x fp16 W -> out + bias
__global__ void __launch_bounds__(256) proj_out(const float* __restrict__ bvec,
                                                float* __restrict__ Dout) {
    __shared__ uint32_t As2[128 * PLDA];
    __shared__ uint32_t Bs2[64 * PLDB];

    const int tid  = threadIdx.x;
    const int m0   = blockIdx.x * 128;
    const int bn   = blockIdx.y;
    const int warp = tid >> 5, lane = tid & 31;
    const int g = lane >> 2, t = lane & 3;
    const int wm = warp >> 1, wn = warp & 1;

    const int ncol = bn * 64;
    const __half* Wt = g_w16T + (size_t)4 * 65536;

    const int ar16[2] = {tid >> 2, (256 + tid) >> 2};
    const int aseg = tid & 3;
    const int brn = tid >> 2, bseg = tid & 3;

    float acc[2][4][4];
#pragma unroll
    for (int i = 0; i < 2; i++)
#pragma unroll
        for (int j = 0; j < 4; j++)
#pragma unroll
            for (int c = 0; c < 4; c++) acc[i][j][c] = 0.0f;

    uint4 ra16[2], rbw;
#pragma unroll
    for (int i = 0; i < 2; i++)
        ra16[i] = *(const uint4*)(g_wa16 + (size_t)(m0 + ar16[i]) * 256 + aseg * 8);
    rbw = *(const uint4*)(Wt + (size_t)(ncol + brn) * 256 + bseg * 8);
#pragma unroll
    for (int i = 0; i < 2; i++)
        *(uint4*)&As2[ar16[i] * PLDA + aseg * 4] = ra16[i];
    *(uint4*)&Bs2[brn * PLDB + bseg * 4] = rbw;

    for (int it = 0; it < 8; it++) {
        __syncthreads();
        if (it < 7) {
            const int k0 = (it + 1) * 32;
#pragma unroll
            for (int i = 0; i < 2; i++)
                ra16[i] = *(const uint4*)(g_wa16 +
                    (size_t)(m0 + ar16[i]) * 256 + k0 + aseg * 8);
            rbw = *(const uint4*)(Wt + (size_t)(ncol + brn) * 256 + k0 + bseg * 8);
        }
#pragma unroll
        for (int u = 0; u < 2; u++) {
            uint32_t af[2][4], bf[4][2];
#pragma unroll
            for (int i = 0; i < 2; i++) {
                const int rb2 = wm * 32 + i * 16;
                af[i][0] = As2[(rb2 + g) * PLDA + u * 8 + t];
                af[i][1] = As2[(rb2 + g + 8) * PLDA + u * 8 + t];
                af[i][2] = As2[(rb2 + g) * PLDA + u * 8 + t + 4];
                af[i][3] = As2[(rb2 + g + 8) * PLDA + u * 8 + t + 4];
            }
#pragma unroll
            for (int j = 0; j < 4; j++) {
                const int nb = wn * 32 + j * 8;
                bf[j][0] = Bs2[(nb + g) * PLDB + u * 8 + t];
                bf[j][1] = Bs2[(nb + g) * PLDB + u * 8 + t + 4];
            }
#pragma unroll
            for (int i = 0; i < 2; i++)
#pragma unroll
                for (int j = 0; j < 4; j++) mma16(acc[i][j], af[i], bf[j][0], bf[j][1]);
        }
        __syncthreads();
        if (it < 7) {
#pragma unroll
            for (int i = 0; i < 2; i++)
                *(uint4*)&As2[ar16[i] * PLDA + aseg * 4] = ra16[i];
            *(uint4*)&Bs2[brn * PLDB + bseg * 4] = rbw;
        }
    }

#pragma unroll
    for (int i = 0; i < 2; i++) {
        const int r0 = m0 + wm * 32 + i * 16 + g;
#pragma unroll
        for (int j = 0; j < 4; j++) {
            const int cb = ncol + wn * 32 + j * 8 + 2 * t;
            const float* c = acc[i][j];
#pragma unroll
            for (int half = 0; half < 2; half++) {
                const int row = r0 + half * 8;
                *(float2*)&Dout[(size_t)row * 256 + cb] = make_float2(
                    c[half * 2 + 0] + bvec[cb], c[half * 2 + 1] + bvec[cb + 1]);
            }
        }
    }
}

// ---------------- fp16 flash attention, fixed-offset softmax ------------------
// grid (Q/128, H, B), 256 thr (8 warps). Warp w owns q-rows w*16..w*16+15.
#define QS2 20
#define KS2 20
#define VS2 36
#define SQ_OFF  0
#define SK_OFF  (SQ_OFF + 128 * QS2)
#define SV_OFF  (SK_OFF + 2 * 64 * KS2)
#define SM_WORDS (SV_OFF + 2 * 32 * VS2)   // 29696 B

__global__ void __launch_bounds__(256) attn_flash(const float* __restrict__ bias,
                                                  const float* __restrict__ nbb) {
    __shared__ uint32_t sm[SM_WORDS];
    uint32_t* qsm2 = sm + SQ_OFF;

    const int tid = threadIdx.x;
    const int q0  = blockIdx.x * 128;
    const int h   = blockIdx.y;
    const int b   = blockIdx.z;
    const int warp = tid >> 5, lane = tid & 31;
    const int g = lane >> 2, t = lane & 3;

    const __half* qb  = g_q16 + ((size_t)(b * Q_ + q0)) * C_ + h * HD_;
    const __half* kb  = g_k16 + ((size_t)b * KK_) * C_ + h * HD_;
    const __half* vtb = g_vT16 + ((size_t)(b * 256 + h * HD_)) * KK_;
    const uint32_t smu = (uint32_t)__cvta_generic_to_shared(sm);

#pragma unroll
    for (int i = 0; i < 2; i++) {
        int v = i * 256 + tid;
        int r = v >> 2, seg = v & 3;
        uint4 d4 = *(const uint4*)(qb + (size_t)r * C_ + seg * 8);
        *(uint4*)&qsm2[r * QS2 + seg * 4] = d4;
    }

    auto issue_kv = [&](int kc) {
        const int st = kc & 1;
        {   int r = tid >> 2, seg = tid & 3;
            cp16(smu + (SK_OFF + st * 64 * KS2 + r * KS2 + seg * 4) * 4,
                 kb + (size_t)(kc * 64 + r) * C_ + seg * 8);
        }
        {   int d = tid >> 3, seg = tid & 7;
            cp16(smu + (SV_OFF + st * 32 * VS2 + d * VS2 + seg * 4) * 4,
                 vtb + (size_t)d * KK_ + kc * 64 + seg * 8);
        }
    };

    issue_kv(0); CP_COMMIT();
    issue_kv(1); CP_COMMIT();
    __syncthreads();

    uint32_t af[2][4];
#pragma unroll
    for (int u = 0; u < 2; u++) {
        af[u][0] = qsm2[(warp * 16 + g) * QS2 + u * 8 + t];
        af[u][1] = qsm2[(warp * 16 + g + 8) * QS2 + u * 8 + t];
        af[u][2] = qsm2[(warp * 16 + g) * QS2 + u * 8 + t + 4];
        af[u][3] = qsm2[(warp * 16 + g + 8) * QS2 + u * 8 + t + 4];
    }

    const int r0 = warp * 16 + g, r1 = r0 + 8;
    const float* brow0 = bias + ((size_t)(b * Q_ + q0 + r0)) * KK_;
    const float* brow1 = bias + ((size_t)(b * Q_ + q0 + r1)) * KK_;
    const float* nrow0 = nbb + ((size_t)(h * Q_ + q0 + r0)) * KK_;
    const float* nrow1 = nbb + ((size_t)(h * Q_ + q0 + r1)) * KK_;

    float rs0 = 0.0f, rs1 = 0.0f;    // plain sums (fixed offset -> no rescale)
    float o[4][4];
#pragma unroll
    for (int nf = 0; nf < 4; nf++)
#pragma unroll
        for (int c = 0; c < 4; c++) o[nf][c] = 0.0f;

    for (int kc = 0; kc < 8; kc++) {
        const int st = kc & 1;
        const uint32_t* Kb2 = sm + SK_OFF + st * 64 * KS2;
        const uint32_t* Vb2 = sm + SV_OFF + st * 32 * VS2;
        CP_WAIT1();
        __syncthreads();

        // ---- S = q k^T : 16 rows x 64 keys ----
        float s[8][4];
#pragma unroll
        for (int j = 0; j < 8; j++)
#pragma unroll
            for (int c = 0; c < 4; c++) s[j][c] = 0.0f;
#pragma unroll
        for (int u = 0; u < 2; u++)
#pragma unroll
            for (int j = 0; j < 8; j++) {
                uint32_t b0 = Kb2[(j * 8 + g) * KS2 + u * 8 + t];
                uint32_t b1 = Kb2[(j * 8 + g) * KS2 + u * 8 + t + 4];
                mma16(s[j], af[u], b0, b1);
            }

        // ---- bias + nbb + fixed-offset exp + partial sums ----
#pragma unroll
        for (int j = 0; j < 8; j++) {
            const int col = kc * 64 + j * 8 + 2 * t;
            float2 b0 = *(const float2*)(brow0 + col);
            float2 n0 = *(const float2*)(nrow0 + col);
            float2 b1 = *(const float2*)(brow1 + col);
            float2 n1 = *(const float2*)(nrow1 + col);
            s[j][0] = __expf(s[j][0] + b0.x + n0.x - SOFT_OFF);
            s[j][1] = __expf(s[j][1] + b0.y + n0.y - SOFT_OFF);
            s[j][2] = __expf(s[j][2] + b1.x + n1.x - SOFT_OFF);
            s[j][3] = __expf(s[j][3] + b1.y + n1.y - SOFT_OFF);
            rs0 += s[j][0] + s[j][1];
            rs1 += s[j][2] + s[j][3];
        }

        // ---- PV: P C-frag == fp16 A-frag, zero shuffles ----
#pragma unroll
        for (int u = 0; u < 4; u++) {
            uint32_t pa[4];
            pa[0] = packh2(s[2 * u][0], s[2 * u][1]);
            pa[1] = packh2(s[2 * u][2], s[2 * u][3]);
            pa[2] = packh2(s[2 * u + 1][0], s[2 * u + 1][1]);
            pa[3] = packh2(s[2 * u + 1][2], s[2 * u + 1][3]);
#pragma unroll
            for (int nf = 0; nf < 4; nf++) {
                uint32_t b0 = Vb2[(nf * 8 + g) * VS2 + u * 8 + t];
                uint32_t b1 = Vb2[(nf * 8 + g) * VS2 + u * 8 + t + 4];
                mma16(o[nf], pa, b0, b1);
            }
        }
        __syncthreads();
        if (kc + 2 < 8) issue_kv(kc + 2);
        CP_COMMIT();
    }

    // ---- deferred quad reduction of row sums ----
    rs0 += __shfl_xor_sync(0xffffffff, rs0, 1);
    rs0 += __shfl_xor_sync(0xffffffff, rs0, 2);
    rs1 += __shfl_xor_sync(0xffffffff, rs1, 1);
    rs1 += __shfl_xor_sync(0xffffffff, rs1, 2);

    const float inv0 = 1.0f / rs0, inv1 = 1.0f / rs1;
#pragma unroll
    for (int half = 0; half < 2; half++) {
        const int r = half ? r1 : r0;
        const float inv = half ? inv1 : inv0;
        const size_t obase = ((size_t)(b * Q_ + q0 + r)) * C_ + h * HD_;
#pragma unroll
        for (int nf = 0; nf < 4; nf++) {
            const int d = nf * 8 + 2 * t;
            float2 ga = *(const float2*)&g_gate[obase + d];
            *(__half2*)&g_wa16[obase + d] = __floats2half2_rn(
                o[nf][half * 2] * inv * ga.x,
                o[nf][half * 2 + 1] * inv * ga.y);
        }
    }
}

// ---------------- launch ------------------------------------------------------
extern "C" void kernel_launch(void* const* d_in, const int* in_sizes, int n_in,
                              void* d_out, int out_size) {
    const float* q_data    = (const float*)d_in[0];
    const float* m_data    = (const float*)d_in[1];
    const float* bias      = (const float*)d_in[2];
    const float* nbb       = (const float*)d_in[3];
    const float* query_w   = (const float*)d_in[4];
    const float* key_w     = (const float*)d_in[5];
    const float* value_w   = (const float*)d_in[6];
    const float* gating_w  = (const float*)d_in[7];
    const float* gating_b  = (const float*)d_in[8];
    const float* output_w  = (const float*)d_in[9];
    const float* output_b  = (const float*)d_in[10];
    float* out = (float*)d_out;

    wprep<<<dim3(256, 5), 256>>>(query_w, key_w, value_w, gating_w, output_w);
    proj01<<<dim3(256, 8, 2), 256>>>(q_data, m_data, gating_b);
    attn_flash<<<dim3(Q_ / 128, H_, B_), 256>>>(bias, nbb);
    proj_out<<<dim3(256, 4), 256>>>(output_b, out);
}